// round 3
// baseline (speedup 1.0000x reference)
#include <cuda_runtime.h>
#include <cuda_bf16.h>

#define B_       128
#define H1OUT    48
#define H2OUT    16
#define H3OUT    13
#define HW3      (H3OUT*H3OUT)     // 169
#define NROWS    (B_*HW3)          // 21632
#define NEMB     512
#define EMB      64

typedef unsigned long long ull;

// ---- packed fp32x2 helpers (Blackwell FFMA2) --------------------------------
__device__ __forceinline__ void fma2(ull& d, ull a, ull b) {
    asm("fma.rn.f32x2 %0, %1, %2, %0;" : "+l"(d) : "l"(a), "l"(b));
}
__device__ __forceinline__ ull add2(ull a, ull b) {
    ull r; asm("add.rn.f32x2 %0, %1, %2;" : "=l"(r) : "l"(a), "l"(b)); return r;
}
__device__ __forceinline__ ull pack2(float a, float b) {
    ull r; asm("mov.b64 %0, {%1, %2};" : "=l"(r) : "f"(a), "f"(b)); return r;
}
__device__ __forceinline__ float2 unpack2(ull v) {
    float2 r; asm("mov.b64 {%0, %1}, %2;" : "=f"(r.x), "=f"(r.y) : "l"(v)); return r;
}
union F4U { float4 f; ull u[2]; };

// ---- scratch ----------------------------------------------------------------
__device__ __align__(16) float g_z1[B_*64*H1OUT*H1OUT];
__device__ __align__(16) float g_z2[B_*128*H2OUT*H2OUT];
__device__ __align__(16) float g_z3t[NROWS*EMB];
__device__ float g_vqs[2*NROWS];
__device__ int   g_vqi[2*NROWS];

// ===========================================================================
// conv1: x[128,3,192,192] * w1[64,3,8,8] s4 p2 +relu -> g_z1[128,64,48,48]
// block: (tile 8x8 out, b), 256 thr; thread 4oc x 4sp; pair-by-oc f32x2.
// smem: w[192][68] + x dup-phase [3ci][4p][36][10 pairs]
// ===========================================================================
#define C1_WPAD 68
#define C1_WS   (192*C1_WPAD)            // floats
#define C1_XD   (3*4*36*10)              // pairs
#define C1_SMEM ((C1_WS + 2*C1_XD)*4)

__global__ __launch_bounds__(256) void conv1_kernel(
    const float* __restrict__ x, const float* __restrict__ w1,
    const float* __restrict__ b1)
{
    extern __shared__ float sm[];
    float* w_s = sm;
    float* xd  = sm + C1_WS;

    const int tile = blockIdx.x;
    const int b    = blockIdx.y;
    const int oh0  = (tile / 6) * 8;
    const int ow0  = (tile % 6) * 8;
    const int ih0  = oh0*4 - 2;
    const int iw0  = ow0*4 - 2;
    const int t    = threadIdx.x;

    for (int idx = t; idx < 64*192; idx += 256) {
        int oc = idx / 192, k = idx % 192;
        w_s[k*C1_WPAD + oc] = w1[idx];
    }
    for (int idx = t; idx < 3*36*36; idx += 256) {
        int ci = idx / 1296, rem = idx % 1296;
        int py = rem / 36,  px = rem % 36;
        int ih = ih0 + py,  iw = iw0 + px;
        float v = 0.f;
        if (ih >= 0 && ih < 192 && iw >= 0 && iw < 192)
            v = x[((b*3 + ci)*192 + ih)*192 + iw];
        int p = px & 3, xp = px >> 2;
        *(float2*)&xd[2*((((ci*4 + p)*36 + py)*10) + xp)] = make_float2(v, v);
    }
    __syncthreads();

    const int ocg = t >> 4;                 // 0..15 -> oc0 = ocg*4
    const int sg  = t & 15;
    const int sy  = sg >> 1;
    const int sx0 = (sg & 1) * 4;

    ull acc[2][4];
    #pragma unroll
    for (int i = 0; i < 2; i++)
        #pragma unroll
        for (int j = 0; j < 4; j++) acc[i][j] = 0ull;

    const float4* w4 = (const float4*)w_s;

    for (int ci = 0; ci < 3; ci++) {
        #pragma unroll 2
        for (int kh = 0; kh < 8; kh++) {
            const float* r0 = &xd[2*(((ci*4 + 0)*36 + sy*4 + kh)*10)];
            const float* r1 = &xd[2*(((ci*4 + 1)*36 + sy*4 + kh)*10)];
            const float* r2 = &xd[2*(((ci*4 + 2)*36 + sy*4 + kh)*10)];
            const float* r3 = &xd[2*(((ci*4 + 3)*36 + sy*4 + kh)*10)];
            const float* rp[4] = {r0, r1, r2, r3};
            #pragma unroll
            for (int kw = 0; kw < 8; kw++) {
                const int q = kw >> 2, p = kw & 3;
                F4U w; w.f = w4[(ci*64 + kh*8 + kw)*17 + ocg];
                #pragma unroll
                for (int j = 0; j < 4; j++) {
                    ull xs = *(const ull*)&rp[p][2*(sx0 + j + q)];
                    fma2(acc[0][j], w.u[0], xs);
                    fma2(acc[1][j], w.u[1], xs);
                }
            }
        }
    }

    const int oc0 = ocg * 4;
    #pragma unroll
    for (int i = 0; i < 2; i++) {
        float blo = __ldg(&b1[oc0 + 2*i]);
        float bhi = __ldg(&b1[oc0 + 2*i + 1]);
        #pragma unroll
        for (int j = 0; j < 4; j++) {
            float2 v = unpack2(acc[i][j]);
            float vlo = fmaxf(v.x + blo, 0.f);
            float vhi = fmaxf(v.y + bhi, 0.f);
            g_z1[((b*64 + oc0+2*i  )*H1OUT + oh0+sy)*H1OUT + ow0+sx0+j] = vlo;
            g_z1[((b*64 + oc0+2*i+1)*H1OUT + oh0+sy)*H1OUT + ow0+sx0+j] = vhi;
        }
    }
}

// ===========================================================================
// conv2: g_z1 * w2[128,64,6,6] s3 p2 +relu -> g_z2[128,128,16,16]
// block: (rowhalf, ocg2, b): 64oc x 8x16 sp; 256 thr; thread 8oc x 4sp.
// ci chunks of 4; smem: w[144][68] + x dup-phase [4ci][3p][27][18 pairs]
// ===========================================================================
#define C2_WPAD 68
#define C2_WS   (144*C2_WPAD)
#define C2_XD   (4*3*27*18)
#define C2_SMEM ((C2_WS + 2*C2_XD)*4)

__global__ __launch_bounds__(256) void conv2_kernel(
    const float* __restrict__ w2, const float* __restrict__ b2)
{
    extern __shared__ float sm[];
    float* w_s = sm;
    float* xd  = sm + C2_WS;

    const int oh0 = blockIdx.x * 8;
    const int ocb = blockIdx.y * 64;
    const int b   = blockIdx.z;
    const int ih0 = oh0*3 - 2;
    const int t   = threadIdx.x;

    const int ocg = t >> 5;                 // 0..7 -> 8 oc each
    const int spg = t & 31;
    const int sy  = spg >> 2;               // 0..7
    const int sx0 = (spg & 3) * 4;          // 0,4,8,12

    ull acc[4][4];
    #pragma unroll
    for (int i = 0; i < 4; i++)
        #pragma unroll
        for (int j = 0; j < 4; j++) acc[i][j] = 0ull;

    const float4* w4 = (const float4*)w_s;

    for (int cc = 0; cc < 16; cc++) {       // ci chunks of 4
        __syncthreads();
        for (int idx = t; idx < 64*144; idx += 256) {
            int oc = idx / 144, k = idx % 144;
            w_s[k*C2_WPAD + oc] = w2[(ocb + oc)*2304 + cc*144 + k];
        }
        for (int idx = t; idx < 4*27*52; idx += 256) {
            int ci = idx / 1404, rem = idx % 1404;
            int py = rem / 52, px = rem % 52;
            int ih = ih0 + py, iw = px - 2;
            float v = 0.f;
            if (ih >= 0 && ih < 48 && iw >= 0 && iw < 48)
                v = g_z1[((b*64 + cc*4 + ci)*48 + ih)*48 + iw];
            int p = px % 3, xp = px / 3;
            *(float2*)&xd[2*(((ci*3 + p)*27 + py)*18 + xp)] = make_float2(v, v);
        }
        __syncthreads();

        #pragma unroll 2
        for (int ci = 0; ci < 4; ci++) {
            #pragma unroll 2
            for (int kh = 0; kh < 6; kh++) {
                const float* r0 = &xd[2*(((ci*3 + 0)*27 + sy*3 + kh)*18)];
                const float* r1 = &xd[2*(((ci*3 + 1)*27 + sy*3 + kh)*18)];
                const float* r2 = &xd[2*(((ci*3 + 2)*27 + sy*3 + kh)*18)];
                const float* rp[3] = {r0, r1, r2};
                #pragma unroll
                for (int kw = 0; kw < 6; kw++) {
                    const int q = kw / 3, p = kw % 3;
                    const int k = ci*36 + kh*6 + kw;
                    F4U wa; wa.f = w4[k*17 + ocg*2];
                    F4U wb; wb.f = w4[k*17 + ocg*2 + 1];
                    #pragma unroll
                    for (int j = 0; j < 4; j++) {
                        ull xs = *(const ull*)&rp[p][2*(sx0 + j + q)];
                        fma2(acc[0][j], wa.u[0], xs);
                        fma2(acc[1][j], wa.u[1], xs);
                        fma2(acc[2][j], wb.u[0], xs);
                        fma2(acc[3][j], wb.u[1], xs);
                    }
                }
            }
        }
    }

    const int oc0 = ocb + ocg*8;
    #pragma unroll
    for (int i = 0; i < 4; i++) {
        float blo = __ldg(&b2[oc0 + 2*i]);
        float bhi = __ldg(&b2[oc0 + 2*i + 1]);
        #pragma unroll
        for (int j = 0; j < 4; j++) {
            float2 v = unpack2(acc[i][j]);
            float vlo = fmaxf(v.x + blo, 0.f);
            float vhi = fmaxf(v.y + bhi, 0.f);
            g_z2[((b*128 + oc0+2*i  )*H2OUT + oh0+sy)*H2OUT + sx0+j] = vlo;
            g_z2[((b*128 + oc0+2*i+1)*H2OUT + oh0+sy)*H2OUT + sx0+j] = vhi;
        }
    }
}

// ===========================================================================
// conv3: g_z2 * w3[64,128,4,4] s1 p0 -> g_z3t[row][64]
// block/batch, 192 thr (169 active), 64 acc as 32 f32x2 pairs (pair-by-oc).
// ===========================================================================
#define C3_WPAD 68
#define C3_SMEM ((256*C3_WPAD + 16*256)*4)

__global__ __launch_bounds__(192) void conv3_kernel(
    const float* __restrict__ w3, const float* __restrict__ b3)
{
    extern __shared__ float sm[];
    float* w_s = sm;
    float* x_s = sm + 256*C3_WPAD;

    const int b = blockIdx.x;
    const int t = threadIdx.x;

    ull acc[32];
    #pragma unroll
    for (int o = 0; o < 32; o++) acc[o] = 0ull;

    const int oh = t / 13;
    const int ow = t % 13;
    const float4* w4 = (const float4*)w_s;

    for (int cc = 0; cc < 8; cc++) {
        __syncthreads();
        for (int idx = t; idx < 64*256; idx += 192) {
            int oc = idx / 256, k = idx % 256;
            w_s[k*C3_WPAD + oc] = w3[oc*2048 + cc*256 + k];
        }
        for (int idx = t; idx < 16*256; idx += 192)
            x_s[idx] = g_z2[b*128*256 + cc*16*256 + idx];
        __syncthreads();

        if (t < 169) {
            for (int c = 0; c < 16; c++) {
                #pragma unroll
                for (int kh = 0; kh < 4; kh++) {
                    #pragma unroll
                    for (int kw = 0; kw < 4; kw++) {
                        float xv = x_s[(c*16 + oh + kh)*16 + ow + kw];
                        ull xs = pack2(xv, xv);
                        const int k = c*16 + kh*4 + kw;
                        #pragma unroll
                        for (int o = 0; o < 16; o++) {
                            F4U w; w.f = w4[k*17 + o];
                            fma2(acc[2*o  ], w.u[0], xs);
                            fma2(acc[2*o+1], w.u[1], xs);
                        }
                    }
                }
            }
        }
    }

    if (t < 169) {
        float* zo = &g_z3t[(b*HW3 + t)*EMB];
        #pragma unroll
        for (int o = 0; o < 32; o++) {
            float2 v = unpack2(acc[o]);
            zo[4*(o>>1) + (o&1)*2 + 0] = v.x + __ldg(&b3[4*(o>>1) + (o&1)*2 + 0]);
            zo[4*(o>>1) + (o&1)*2 + 1] = v.y + __ldg(&b3[4*(o>>1) + (o&1)*2 + 1]);
        }
    }
}

// ===========================================================================
// VQ partial argmin: grid(85 rowblocks, 2 code chunks), 256 thr.
// Each block: 256 rows x 256 codes; codebook chunk in smem (66KB -> 3 blk/SM).
// ===========================================================================
#define VQ_SMEM ((256*EMB + 256)*4)

__global__ __launch_bounds__(256) void vq_kernel(const float* __restrict__ cb)
{
    extern __shared__ float sm[];
    float* cb_s = sm;
    float* cn_s = sm + 256*EMB;

    const int chunk = blockIdx.y;
    const int t = threadIdx.x;

    for (int idx = t; idx < 256*EMB; idx += 256)
        cb_s[idx] = cb[chunk*256*EMB + idx];
    __syncthreads();
    {
        float s = 0.f;
        const float* cp = &cb_s[t*EMB];
        #pragma unroll 8
        for (int j = 0; j < EMB; j++) s += cp[j]*cp[j];
        cn_s[t] = s;
    }
    __syncthreads();

    const int row = blockIdx.x*256 + t;
    if (row >= NROWS) return;

    ull zu[32];
    const float4* zp = (const float4*)&g_z3t[row*EMB];
    #pragma unroll
    for (int i = 0; i < 16; i++) {
        F4U v; v.f = zp[i];
        zu[2*i] = v.u[0]; zu[2*i+1] = v.u[1];
    }

    float best = 3.402823466e38f;
    int bi = 0;
    for (int k = 0; k < 256; k++) {
        const float4* cp = (const float4*)&cb_s[k*EMB];
        ull d0 = 0ull, d1 = 0ull, d2 = 0ull, d3 = 0ull;
        #pragma unroll
        for (int i = 0; i < 8; i++) {
            F4U ca; ca.f = cp[2*i];
            F4U cb2; cb2.f = cp[2*i+1];
            fma2(d0, ca.u[0],  zu[4*i]);
            fma2(d1, ca.u[1],  zu[4*i+1]);
            fma2(d2, cb2.u[0], zu[4*i+2]);
            fma2(d3, cb2.u[1], zu[4*i+3]);
        }
        float2 s = unpack2(add2(add2(d0, d1), add2(d2, d3)));
        float score = cn_s[k] - 2.f*(s.x + s.y);
        if (score < best) { best = score; bi = k; }
    }
    g_vqs[chunk*NROWS + row] = best;
    g_vqi[chunk*NROWS + row] = chunk*256 + bi;
}

// ===========================================================================
// output: zero-fill (float4) + one-hot scatter with cross-chunk argmin merge
// ===========================================================================
#define OUT_N4 (B_*NEMB*HW3/4)   // 2768896

__global__ __launch_bounds__(256) void zero_kernel(float4* __restrict__ out4)
{
    int idx = blockIdx.x*256 + threadIdx.x;
    float4 z = make_float4(0.f, 0.f, 0.f, 0.f);
    #pragma unroll
    for (int i = 0; i < 8; i++)
        out4[idx + i*(1352*256)] = z;
}

__global__ __launch_bounds__(256) void scatter_kernel(float* __restrict__ out)
{
    int row = blockIdx.x*256 + threadIdx.x;
    if (row >= NROWS) return;
    float s0 = g_vqs[row], s1 = g_vqs[NROWS + row];
    int k = (s0 <= s1) ? g_vqi[row] : g_vqi[NROWS + row];
    int b = row / HW3, hw = row % HW3;
    out[((size_t)(b*NEMB + k))*HW3 + hw] = 1.0f;
}

// ===========================================================================
extern "C" void kernel_launch(void* const* d_in, const int* in_sizes, int n_in,
                              void* d_out, int out_size)
{
    const float* x  = (const float*)d_in[0];
    const float* w1 = (const float*)d_in[1];
    const float* b1 = (const float*)d_in[2];
    const float* w2 = (const float*)d_in[3];
    const float* b2 = (const float*)d_in[4];
    const float* w3 = (const float*)d_in[5];
    const float* b3 = (const float*)d_in[6];
    const float* cb = (const float*)d_in[7];
    float* out = (float*)d_out;

    cudaFuncSetAttribute(conv1_kernel, cudaFuncAttributeMaxDynamicSharedMemorySize, C1_SMEM);
    cudaFuncSetAttribute(conv2_kernel, cudaFuncAttributeMaxDynamicSharedMemorySize, C2_SMEM);
    cudaFuncSetAttribute(conv3_kernel, cudaFuncAttributeMaxDynamicSharedMemorySize, C3_SMEM);
    cudaFuncSetAttribute(vq_kernel,    cudaFuncAttributeMaxDynamicSharedMemorySize, VQ_SMEM);

    conv1_kernel<<<dim3(36, B_), 256, C1_SMEM>>>(x, w1, b1);
    conv2_kernel<<<dim3(2, 2, B_), 256, C2_SMEM>>>(w2, b2);
    conv3_kernel<<<B_, 192, C3_SMEM>>>(w3, b3);
    vq_kernel<<<dim3(85, 2), 256, VQ_SMEM>>>(cb);
    zero_kernel<<<1352, 256>>>((float4*)out);
    scatter_kernel<<<85, 256>>>(out);
}

// round 4
// speedup vs baseline: 1.5041x; 1.5041x over previous
#include <cuda_runtime.h>
#include <cuda_bf16.h>

#define B_       128
#define H3OUT    13
#define HW3      (H3OUT*H3OUT)     // 169
#define NROWS    (B_*HW3)          // 21632
#define NEMB     512
#define EMB      64
#define NCHUNK   8                 // vq code chunks

typedef unsigned long long ull;

// ---- packed fp32x2 (FFMA2) helpers ----------------------------------------
__device__ __forceinline__ void fma2(ull& d, ull a, ull b) {
    asm("fma.rn.f32x2 %0, %1, %2, %0;" : "+l"(d) : "l"(a), "l"(b));
}
__device__ __forceinline__ ull pack2(float a, float b) {
    ull r; asm("mov.b64 %0, {%1, %2};" : "=l"(r) : "f"(a), "f"(b)); return r;
}
__device__ __forceinline__ float2 unpack2(ull v) {
    float2 r; asm("mov.b64 {%0, %1}, %2;" : "=f"(r.x), "=f"(r.y) : "l"(v)); return r;
}
union F4U { float4 f; ull u[2]; };

// ---- scratch ----------------------------------------------------------------
__device__ __align__(16) float g_z1[B_*64*48*48];
__device__ __align__(16) float g_z2[B_*128*16*16];
__device__ __align__(16) float g_z3t[NROWS*EMB];
__device__ float g_vqs[NCHUNK*NROWS];
__device__ int   g_vqi[NCHUNK*NROWS];

// ===========================================================================
// conv1: x[128,3,192,192] * w1[64,3,8,8] s4 p2 +relu -> g_z1[128,64,48,48]
// grid(9 tiles, 128 b), block 256. tile = 16x16 out, 64 oc.
// thread: 16oc x (1row x 4col interleaved). w in smem [k=192][68], broadcast.
// x phase-split: [ci][p=c%4][iy 68][ix 17]
// ===========================================================================
#define C1_WOC  68
#define C1_WS   (192*C1_WOC)
#define C1_XS   (3*4*68*17)
#define C1_SMEM ((C1_WS + C1_XS)*4)

__global__ __launch_bounds__(256, 2) void conv1_kernel(
    const float* __restrict__ x, const float* __restrict__ w1,
    const float* __restrict__ b1)
{
    extern __shared__ float sm[];
    float* w_s = sm;
    float* xd  = sm + C1_WS;

    const int tile = blockIdx.x;
    const int b    = blockIdx.y;
    const int oh0  = (tile / 3) * 16;
    const int ow0  = (tile % 3) * 16;
    const int t    = threadIdx.x;

    // weights: transpose-load [oc][k] -> [k][oc]
    for (int idx = t; idx < 64*48; idx += 256) {
        int oc = idx / 48, k4 = idx % 48;
        float4 w = *(const float4*)&w1[oc*192 + k4*4];
        w_s[(4*k4+0)*C1_WOC + oc] = w.x;
        w_s[(4*k4+1)*C1_WOC + oc] = w.y;
        w_s[(4*k4+2)*C1_WOC + oc] = w.z;
        w_s[(4*k4+3)*C1_WOC + oc] = w.w;
    }
    // x patch 68x68 per ci, zero-padded, phase-split by col%4
    const int gy0 = oh0*4 - 2, gx0 = ow0*4 - 2;
    for (int idx = t; idx < 3*68*68; idx += 256) {
        int ci = idx / 4624, rem = idx % 4624;
        int iy = rem / 68,  cp  = rem % 68;
        int gy = gy0 + iy,  gx  = gx0 + cp;
        float v = 0.f;
        if (gy >= 0 && gy < 192 && gx >= 0 && gx < 192)
            v = x[((b*3 + ci)*192 + gy)*192 + gx];
        xd[((ci*4 + (cp & 3))*68 + iy)*17 + (cp >> 2)] = v;
    }
    __syncthreads();

    const int ocg = t >> 6;        // 0..3
    const int sg  = t & 63;
    const int sy  = sg >> 2;       // 0..15
    const int sx0 = sg & 3;
    const int oc0 = ocg * 16;

    ull acc[8][4];
    #pragma unroll
    for (int i = 0; i < 8; i++)
        #pragma unroll
        for (int j = 0; j < 4; j++) acc[i][j] = 0ull;

    #pragma unroll 1
    for (int ci = 0; ci < 3; ci++) {
        #pragma unroll 1
        for (int kh = 0; kh < 8; kh++) {
            const int iy = sy*4 + kh;
            #pragma unroll
            for (int kw = 0; kw < 8; kw++) {
                const int p = kw & 3, q = kw >> 2;
                const float* xr = &xd[((ci*4 + p)*68 + iy)*17 + sx0 + q];
                ull xs[4];
                #pragma unroll
                for (int j = 0; j < 4; j++) { float v = xr[4*j]; xs[j] = pack2(v, v); }
                const float* wr = &w_s[(ci*64 + kh*8 + kw)*C1_WOC + oc0];
                #pragma unroll
                for (int u = 0; u < 4; u++) {
                    F4U w; w.f = *(const float4*)&wr[4*u];
                    #pragma unroll
                    for (int j = 0; j < 4; j++) {
                        fma2(acc[2*u  ][j], w.u[0], xs[j]);
                        fma2(acc[2*u+1][j], w.u[1], xs[j]);
                    }
                }
            }
        }
    }

    const int oy = oh0 + sy;
    #pragma unroll
    for (int u = 0; u < 4; u++)
        #pragma unroll
        for (int h = 0; h < 2; h++) {
            int oca = oc0 + 4*u + 2*h;
            float ba = __ldg(&b1[oca]), bb = __ldg(&b1[oca+1]);
            #pragma unroll
            for (int j = 0; j < 4; j++) {
                float2 v = unpack2(acc[2*u+h][j]);
                int ox = ow0 + sx0 + 4*j;
                g_z1[((b*64 + oca  )*48 + oy)*48 + ox] = fmaxf(v.x + ba, 0.f);
                g_z1[((b*64 + oca+1)*48 + oy)*48 + ox] = fmaxf(v.y + bb, 0.f);
            }
        }
}

// ===========================================================================
// conv2: g_z1 * w2[128,64,6,6] s3 p2 +relu -> g_z2[128,128,16,16]
// grid(128 b), block 512. full 16x16 out x 128 oc; ci chunks of 4.
// thread: 16oc x (1row x 4col). w [k=144][132] broadcast; x [ci][p=c%3][51][17]
// ===========================================================================
#define C2_WOC  132
#define C2_WS   (144*C2_WOC)
#define C2_XS   (4*3*51*17)
#define C2_SMEM ((C2_WS + C2_XS)*4)

__global__ __launch_bounds__(512, 1) void conv2_kernel(
    const float* __restrict__ w2, const float* __restrict__ b2)
{
    extern __shared__ float sm[];
    float* w_s = sm;
    float* xd  = sm + C2_WS;

    const int b = blockIdx.x;
    const int t = threadIdx.x;

    const int ocg = t >> 6;        // 0..7
    const int sg  = t & 63;
    const int sy  = sg >> 2;       // 0..15
    const int sx0 = sg & 3;
    const int oc0 = ocg * 16;

    ull acc[8][4];
    #pragma unroll
    for (int i = 0; i < 8; i++)
        #pragma unroll
        for (int j = 0; j < 4; j++) acc[i][j] = 0ull;

    #pragma unroll 1
    for (int cc = 0; cc < 16; cc++) {       // ci chunks of 4
        __syncthreads();
        for (int idx = t; idx < 128*36; idx += 512) {
            int oc = idx / 36, k4 = idx % 36;
            float4 w = *(const float4*)&w2[oc*2304 + cc*144 + k4*4];
            w_s[(4*k4+0)*C2_WOC + oc] = w.x;
            w_s[(4*k4+1)*C2_WOC + oc] = w.y;
            w_s[(4*k4+2)*C2_WOC + oc] = w.z;
            w_s[(4*k4+3)*C2_WOC + oc] = w.w;
        }
        for (int idx = t; idx < 4*51*51; idx += 512) {
            int ci = idx / 2601, rem = idx % 2601;
            int iy = rem / 51,  cp  = rem % 51;
            int gy = iy - 2,    gx  = cp - 2;
            float v = 0.f;
            if (gy >= 0 && gy < 48 && gx >= 0 && gx < 48)
                v = g_z1[((b*64 + cc*4 + ci)*48 + gy)*48 + gx];
            int p = cp % 3, ix = cp / 3;
            xd[((ci*3 + p)*51 + iy)*17 + ix] = v;
        }
        __syncthreads();

        #pragma unroll 1
        for (int ci = 0; ci < 4; ci++) {
            #pragma unroll 1
            for (int kh = 0; kh < 6; kh++) {
                const int iy = sy*3 + kh;
                #pragma unroll
                for (int kw = 0; kw < 6; kw++) {
                    const int p = (kw >= 3) ? kw - 3 : kw;
                    const int q = (kw >= 3) ? 1 : 0;
                    const float* xr = &xd[((ci*3 + p)*51 + iy)*17 + sx0 + q];
                    ull xs[4];
                    #pragma unroll
                    for (int j = 0; j < 4; j++) { float v = xr[4*j]; xs[j] = pack2(v, v); }
                    const float* wr = &w_s[(ci*36 + kh*6 + kw)*C2_WOC + oc0];
                    #pragma unroll
                    for (int u = 0; u < 4; u++) {
                        F4U w; w.f = *(const float4*)&wr[4*u];
                        #pragma unroll
                        for (int j = 0; j < 4; j++) {
                            fma2(acc[2*u  ][j], w.u[0], xs[j]);
                            fma2(acc[2*u+1][j], w.u[1], xs[j]);
                        }
                    }
                }
            }
        }
    }

    #pragma unroll
    for (int u = 0; u < 4; u++)
        #pragma unroll
        for (int h = 0; h < 2; h++) {
            int oca = oc0 + 4*u + 2*h;
            float ba = __ldg(&b2[oca]), bb = __ldg(&b2[oca+1]);
            #pragma unroll
            for (int j = 0; j < 4; j++) {
                float2 v = unpack2(acc[2*u+h][j]);
                int ox = sx0 + 4*j;
                g_z2[((b*128 + oca  )*16 + sy)*16 + ox] = fmaxf(v.x + ba, 0.f);
                g_z2[((b*128 + oca+1)*16 + sy)*16 + ox] = fmaxf(v.y + bb, 0.f);
            }
        }
}

// ===========================================================================
// conv3: g_z2 * w3[64,128,4,4] s1 p0 -> g_z3t[row=b*169+s][64]
// grid(128 b), block 256. thread: 16oc x 3 spatial positions; ci chunks 16.
// w [k=256][68] broadcast; x plain [c16][16][16].
// ===========================================================================
#define C3_WOC  68
#define C3_SMEM ((256*C3_WOC + 16*256)*4)

__global__ __launch_bounds__(256, 2) void conv3_kernel(
    const float* __restrict__ w3, const float* __restrict__ b3)
{
    extern __shared__ float sm[];
    float* w_s = sm;
    float* x_s = sm + 256*C3_WOC;

    const int b = blockIdx.x;
    const int t = threadIdx.x;

    const int ocg = t >> 6;        // 0..3
    const int spg = t & 63;
    const int oc0 = ocg * 16;

    int oh[3], ow[3]; bool act[3];
    #pragma unroll
    for (int j = 0; j < 3; j++) {
        int s = spg*3 + j;
        act[j] = (s < HW3);
        oh[j] = act[j] ? s / 13 : 0;
        ow[j] = act[j] ? s % 13 : 0;
    }

    ull acc[8][3];
    #pragma unroll
    for (int i = 0; i < 8; i++)
        #pragma unroll
        for (int j = 0; j < 3; j++) acc[i][j] = 0ull;

    #pragma unroll 1
    for (int cc = 0; cc < 8; cc++) {
        __syncthreads();
        for (int idx = t; idx < 64*64; idx += 256) {
            int oc = idx / 64, k4 = idx % 64;
            float4 w = *(const float4*)&w3[oc*2048 + cc*256 + k4*4];
            w_s[(4*k4+0)*C3_WOC + oc] = w.x;
            w_s[(4*k4+1)*C3_WOC + oc] = w.y;
            w_s[(4*k4+2)*C3_WOC + oc] = w.z;
            w_s[(4*k4+3)*C3_WOC + oc] = w.w;
        }
        for (int idx = t; idx < 16*256; idx += 256)
            x_s[idx] = g_z2[b*128*256 + cc*16*256 + idx];
        __syncthreads();

        #pragma unroll 1
        for (int c = 0; c < 16; c++) {
            #pragma unroll 1
            for (int kh = 0; kh < 4; kh++) {
                #pragma unroll
                for (int kw = 0; kw < 4; kw++) {
                    ull xs[3];
                    #pragma unroll
                    for (int j = 0; j < 3; j++) {
                        float v = x_s[(c*16 + oh[j] + kh)*16 + ow[j] + kw];
                        xs[j] = pack2(v, v);
                    }
                    const float* wr = &w_s[(c*16 + kh*4 + kw)*C3_WOC + oc0];
                    #pragma unroll
                    for (int u = 0; u < 4; u++) {
                        F4U w; w.f = *(const float4*)&wr[4*u];
                        #pragma unroll
                        for (int j = 0; j < 3; j++) {
                            fma2(acc[2*u  ][j], w.u[0], xs[j]);
                            fma2(acc[2*u+1][j], w.u[1], xs[j]);
                        }
                    }
                }
            }
        }
    }

    float bb[16];
    #pragma unroll
    for (int i = 0; i < 16; i++) bb[i] = __ldg(&b3[oc0 + i]);

    #pragma unroll
    for (int j = 0; j < 3; j++) {
        if (!act[j]) continue;
        float* zo = &g_z3t[(b*HW3 + spg*3 + j)*EMB + oc0];
        #pragma unroll
        for (int u = 0; u < 4; u++) {
            float2 a = unpack2(acc[2*u][j]);
            float2 c = unpack2(acc[2*u+1][j]);
            float4 o = make_float4(a.x + bb[4*u], a.y + bb[4*u+1],
                                   c.x + bb[4*u+2], c.y + bb[4*u+3]);
            *(float4*)&zo[4*u] = o;
        }
    }
}

// ===========================================================================
// VQ partial argmin over 8 code chunks of 64: grid(85, 8), block 256.
// ===========================================================================
#define VQ_SMEM ((64*EMB + 64)*4)

__global__ __launch_bounds__(256, 2) void vq_kernel(const float* __restrict__ cb)
{
    extern __shared__ float sm[];
    float* cb_s = sm;
    float* cn_s = sm + 64*EMB;

    const int chunk = blockIdx.y;
    const int t = threadIdx.x;

    for (int idx = t; idx < 64*EMB; idx += 256)
        cb_s[idx] = cb[chunk*64*EMB + idx];
    __syncthreads();
    if (t < 64) {
        float s = 0.f;
        const float* cp = &cb_s[t*EMB];
        #pragma unroll 8
        for (int j = 0; j < EMB; j++) s += cp[j]*cp[j];
        cn_s[t] = s;
    }
    __syncthreads();

    const int row = blockIdx.x*256 + t;
    if (row >= NROWS) return;

    ull zu[32];
    const float4* zp = (const float4*)&g_z3t[row*EMB];
    #pragma unroll
    for (int i = 0; i < 16; i++) {
        F4U v; v.f = zp[i];
        zu[2*i] = v.u[0]; zu[2*i+1] = v.u[1];
    }

    float best = 3.402823466e38f;
    int bi = 0;
    for (int k = 0; k < 64; k++) {
        const float4* cp = (const float4*)&cb_s[k*EMB];
        ull d0 = 0ull, d1 = 0ull, d2 = 0ull, d3 = 0ull;
        #pragma unroll
        for (int i = 0; i < 8; i++) {
            F4U ca; ca.f = cp[2*i];
            F4U cb2; cb2.f = cp[2*i+1];
            fma2(d0, ca.u[0],  zu[4*i]);
            fma2(d1, ca.u[1],  zu[4*i+1]);
            fma2(d2, cb2.u[0], zu[4*i+2]);
            fma2(d3, cb2.u[1], zu[4*i+3]);
        }
        float2 s0 = unpack2(d0), s1 = unpack2(d1), s2 = unpack2(d2), s3 = unpack2(d3);
        float dot = ((s0.x+s0.y) + (s1.x+s1.y)) + ((s2.x+s2.y) + (s3.x+s3.y));
        float score = cn_s[k] - 2.f*dot;
        if (score < best) { best = score; bi = k; }
    }
    g_vqs[chunk*NROWS + row] = best;
    g_vqi[chunk*NROWS + row] = chunk*64 + bi;
}

// ===========================================================================
// output: zero-fill + merge-8 argmin scatter
// ===========================================================================
__global__ __launch_bounds__(256) void zero_kernel(float4* __restrict__ out4)
{
    int idx = blockIdx.x*256 + threadIdx.x;
    float4 z = make_float4(0.f, 0.f, 0.f, 0.f);
    #pragma unroll
    for (int i = 0; i < 8; i++)
        out4[idx + i*(1352*256)] = z;
}

__global__ __launch_bounds__(256) void scatter_kernel(float* __restrict__ out)
{
    int row = blockIdx.x*256 + threadIdx.x;
    if (row >= NROWS) return;
    float best = g_vqs[row];
    int bi = g_vqi[row];
    #pragma unroll
    for (int c = 1; c < NCHUNK; c++) {
        float s = g_vqs[c*NROWS + row];
        int i2 = g_vqi[c*NROWS + row];
        if (s < best) { best = s; bi = i2; }
    }
    int b = row / HW3, hw = row % HW3;
    out[((size_t)(b*NEMB + bi))*HW3 + hw] = 1.0f;
}

// ===========================================================================
extern "C" void kernel_launch(void* const* d_in, const int* in_sizes, int n_in,
                              void* d_out, int out_size)
{
    const float* x  = (const float*)d_in[0];
    const float* w1 = (const float*)d_in[1];
    const float* b1 = (const float*)d_in[2];
    const float* w2 = (const float*)d_in[3];
    const float* b2 = (const float*)d_in[4];
    const float* w3 = (const float*)d_in[5];
    const float* b3 = (const float*)d_in[6];
    const float* cb = (const float*)d_in[7];
    float* out = (float*)d_out;

    cudaFuncSetAttribute(conv1_kernel, cudaFuncAttributeMaxDynamicSharedMemorySize, C1_SMEM);
    cudaFuncSetAttribute(conv2_kernel, cudaFuncAttributeMaxDynamicSharedMemorySize, C2_SMEM);
    cudaFuncSetAttribute(conv3_kernel, cudaFuncAttributeMaxDynamicSharedMemorySize, C3_SMEM);
    cudaFuncSetAttribute(vq_kernel,    cudaFuncAttributeMaxDynamicSharedMemorySize, VQ_SMEM);

    conv1_kernel<<<dim3(9, B_), 256, C1_SMEM>>>(x, w1, b1);
    conv2_kernel<<<B_, 512, C2_SMEM>>>(w2, b2);
    conv3_kernel<<<B_, 256, C3_SMEM>>>(w3, b3);
    vq_kernel<<<dim3(85, NCHUNK), 256, VQ_SMEM>>>(cb);
    zero_kernel<<<1352, 256>>>((float4*)out);
    scatter_kernel<<<85, 256>>>(out);
}